// round 1
// baseline (speedup 1.0000x reference)
#include <cuda_runtime.h>

#define SQ   2048
#define BB   8
#define DD   512
#define HH   8
#define HDIM 64
#define MROWS (SQ*BB)       // 16384
#define NQKV  (3*DD)        // 1536

// Scratch (allocation-free rule: __device__ globals)
__device__ float g_q[(size_t)BB*HH*SQ*HDIM];       // 32 MB, pre-scaled by hd^-0.5
__device__ float g_k[(size_t)BB*HH*SQ*HDIM];       // 32 MB
__device__ float g_v[(size_t)BB*HH*SQ*HDIM];       // 32 MB
__device__ float g_scores[(size_t)BB*HH*SQ*SQ];    // 1 GB
__device__ float g_ctx[(size_t)MROWS*DD];          // 32 MB

// ---------------------------------------------------------------------------
// K1: QKV projection. C[16384,1536] = src[16384,512] @ W^T + b, scattered into
// g_q (scaled), g_k, g_v in [b,h,s,hd] layout.
// ---------------------------------------------------------------------------
__global__ void qkv_gemm(const float* __restrict__ A, const float* __restrict__ W,
                         const float* __restrict__ bias) {
    __shared__ float As[64][17];
    __shared__ float Ws[64][17];
    int tx = threadIdx.x, ty = threadIdx.y;
    int tid = ty * 16 + tx;
    int m0 = blockIdx.y * 64;
    int n0 = blockIdx.x * 64;
    float acc[4][4] = {};
    for (int k0 = 0; k0 < DD; k0 += 16) {
        #pragma unroll
        for (int l = 0; l < 4; l++) {
            int idx = tid + l * 256;
            int r = idx >> 4, c = idx & 15;
            As[r][c] = A[(size_t)(m0 + r) * DD + k0 + c];
            Ws[r][c] = W[(size_t)(n0 + r) * DD + k0 + c];
        }
        __syncthreads();
        #pragma unroll
        for (int kk = 0; kk < 16; kk++) {
            float a[4], b[4];
            #pragma unroll
            for (int r = 0; r < 4; r++) a[r] = As[ty * 4 + r][kk];
            #pragma unroll
            for (int c = 0; c < 4; c++) b[c] = Ws[tx * 4 + c][kk];
            #pragma unroll
            for (int r = 0; r < 4; r++)
                #pragma unroll
                for (int c = 0; c < 4; c++)
                    acc[r][c] += a[r] * b[c];
        }
        __syncthreads();
    }
    #pragma unroll
    for (int r = 0; r < 4; r++) {
        int i = m0 + ty * 4 + r;
        int s = i / BB, b = i % BB;
        #pragma unroll
        for (int c = 0; c < 4; c++) {
            int j = n0 + tx * 4 + c;
            float v = acc[r][c] + bias[j];
            int part = j / DD;
            int jj = j % DD;
            int h = jj / HDIM, dd = jj % HDIM;
            size_t off = ((size_t)(b * HH + h) * SQ + s) * HDIM + dd;
            if (part == 0)      g_q[off] = v * 0.125f;   // hd^-0.5 = 64^-0.5
            else if (part == 1) g_k[off] = v;
            else                g_v[off] = v;
        }
    }
}

// ---------------------------------------------------------------------------
// K2: scores[bh][s][t] = Q[bh][s,:] . K[bh][t,:]   (K-dim = 64, one-shot smem)
// ---------------------------------------------------------------------------
__global__ void scores_gemm() {
    __shared__ float Qs[64][65];
    __shared__ float Ks[64][65];
    int bh = blockIdx.z;
    int t0 = blockIdx.x * 64;
    int s0 = blockIdx.y * 64;
    const float* Q = g_q + (size_t)bh * SQ * HDIM;
    const float* K = g_k + (size_t)bh * SQ * HDIM;
    int tx = threadIdx.x, ty = threadIdx.y;
    int tid = ty * 16 + tx;
    #pragma unroll
    for (int l = 0; l < 16; l++) {
        int idx = tid + l * 256;
        int r = idx >> 6, c = idx & 63;
        Qs[r][c] = Q[(size_t)(s0 + r) * HDIM + c];
        Ks[r][c] = K[(size_t)(t0 + r) * HDIM + c];
    }
    __syncthreads();
    float acc[4][4] = {};
    #pragma unroll 16
    for (int kk = 0; kk < 64; kk++) {
        float a[4], b[4];
        #pragma unroll
        for (int r = 0; r < 4; r++) a[r] = Qs[ty * 4 + r][kk];
        #pragma unroll
        for (int c = 0; c < 4; c++) b[c] = Ks[tx * 4 + c][kk];
        #pragma unroll
        for (int r = 0; r < 4; r++)
            #pragma unroll
            for (int c = 0; c < 4; c++)
                acc[r][c] += a[r] * b[c];
    }
    float* out = g_scores + (size_t)bh * SQ * SQ;
    #pragma unroll
    for (int r = 0; r < 4; r++)
        #pragma unroll
        for (int c = 0; c < 4; c++)
            out[(size_t)(s0 + ty * 4 + r) * SQ + t0 + tx * 4 + c] = acc[r][c];
}

// ---------------------------------------------------------------------------
// K3: in-place row softmax over g_scores (rows of length 2048, regs-resident)
// ---------------------------------------------------------------------------
__global__ void softmax_rows() {
    size_t row = blockIdx.x;
    float* p = g_scores + row * SQ;
    int tid = threadIdx.x;   // 256
    __shared__ float red[256];
    float v[8];
    float m = -1e30f;
    #pragma unroll
    for (int i = 0; i < 8; i++) { v[i] = p[tid + i * 256]; m = fmaxf(m, v[i]); }
    red[tid] = m; __syncthreads();
    for (int s2 = 128; s2 > 0; s2 >>= 1) {
        if (tid < s2) red[tid] = fmaxf(red[tid], red[tid + s2]);
        __syncthreads();
    }
    m = red[0];
    __syncthreads();
    float sum = 0.0f;
    #pragma unroll
    for (int i = 0; i < 8; i++) { v[i] = __expf(v[i] - m); sum += v[i]; }
    red[tid] = sum; __syncthreads();
    for (int s2 = 128; s2 > 0; s2 >>= 1) {
        if (tid < s2) red[tid] += red[tid + s2];
        __syncthreads();
    }
    float inv = 1.0f / red[0];
    #pragma unroll
    for (int i = 0; i < 8; i++) p[tid + i * 256] = v[i] * inv;
}

// ---------------------------------------------------------------------------
// K4: attn_weights[b,s,t] = mean over h of g_scores[b,h,s,t]
// ---------------------------------------------------------------------------
__global__ void head_avg(float* __restrict__ out_attn) {
    size_t i = (size_t)blockIdx.x * blockDim.x + threadIdx.x;
    if (i >= (size_t)BB * SQ * SQ) return;
    size_t b   = i / ((size_t)SQ * SQ);
    size_t rem = i % ((size_t)SQ * SQ);
    float sum = 0.0f;
    #pragma unroll
    for (int h = 0; h < HH; h++)
        sum += g_scores[(size_t)(b * HH + h) * SQ * SQ + rem];
    out_attn[i] = sum * 0.125f;
}

// ---------------------------------------------------------------------------
// K5: ctx[bh][s,:] = attn[bh][s,:] @ V[bh]   (M=2048, N=64, K=2048)
// writes to g_ctx in [s, b, d] layout
// ---------------------------------------------------------------------------
__global__ void ctx_gemm() {
    __shared__ float As[64][17];
    __shared__ float Vs[16][65];
    int bh = blockIdx.z;
    int s0 = blockIdx.y * 64;
    const float* P = g_scores + (size_t)bh * SQ * SQ;
    const float* V = g_v + (size_t)bh * SQ * HDIM;
    int tx = threadIdx.x, ty = threadIdx.y;
    int tid = ty * 16 + tx;
    float acc[4][4] = {};
    for (int k0 = 0; k0 < SQ; k0 += 16) {
        #pragma unroll
        for (int l = 0; l < 4; l++) {
            int idx = tid + l * 256;
            int r = idx >> 4, c = idx & 15;
            As[r][c] = P[(size_t)(s0 + r) * SQ + k0 + c];
        }
        #pragma unroll
        for (int l = 0; l < 4; l++) {
            int idx = tid + l * 256;
            int r = idx >> 6, c = idx & 63;
            Vs[r][c] = V[(size_t)(k0 + r) * HDIM + c];
        }
        __syncthreads();
        #pragma unroll
        for (int kk = 0; kk < 16; kk++) {
            float a[4], b[4];
            #pragma unroll
            for (int r = 0; r < 4; r++) a[r] = As[ty * 4 + r][kk];
            #pragma unroll
            for (int c = 0; c < 4; c++) b[c] = Vs[kk][tx * 4 + c];
            #pragma unroll
            for (int r = 0; r < 4; r++)
                #pragma unroll
                for (int c = 0; c < 4; c++)
                    acc[r][c] += a[r] * b[c];
        }
        __syncthreads();
    }
    int b = bh / HH, h = bh % HH;
    #pragma unroll
    for (int r = 0; r < 4; r++) {
        int s = s0 + ty * 4 + r;
        #pragma unroll
        for (int c = 0; c < 4; c++) {
            int d = tx * 4 + c;
            g_ctx[((size_t)s * BB + b) * DD + h * HDIM + d] = acc[r][c];
        }
    }
}

// ---------------------------------------------------------------------------
// K6: out = ctx @ out_w^T + out_b  (M=16384, N=512, K=512)
// ---------------------------------------------------------------------------
__global__ void out_gemm(const float* __restrict__ W, const float* __restrict__ bias,
                         float* __restrict__ out) {
    __shared__ float As[64][17];
    __shared__ float Ws[64][17];
    int tx = threadIdx.x, ty = threadIdx.y;
    int tid = ty * 16 + tx;
    int m0 = blockIdx.y * 64;
    int n0 = blockIdx.x * 64;
    float acc[4][4] = {};
    for (int k0 = 0; k0 < DD; k0 += 16) {
        #pragma unroll
        for (int l = 0; l < 4; l++) {
            int idx = tid + l * 256;
            int r = idx >> 4, c = idx & 15;
            As[r][c] = g_ctx[(size_t)(m0 + r) * DD + k0 + c];
            Ws[r][c] = W[(size_t)(n0 + r) * DD + k0 + c];
        }
        __syncthreads();
        #pragma unroll
        for (int kk = 0; kk < 16; kk++) {
            float a[4], b[4];
            #pragma unroll
            for (int r = 0; r < 4; r++) a[r] = As[ty * 4 + r][kk];
            #pragma unroll
            for (int c = 0; c < 4; c++) b[c] = Ws[tx * 4 + c][kk];
            #pragma unroll
            for (int r = 0; r < 4; r++)
                #pragma unroll
                for (int c = 0; c < 4; c++)
                    acc[r][c] += a[r] * b[c];
        }
        __syncthreads();
    }
    #pragma unroll
    for (int r = 0; r < 4; r++) {
        int i = m0 + ty * 4 + r;
        #pragma unroll
        for (int c = 0; c < 4; c++) {
            int j = n0 + tx * 4 + c;
            out[(size_t)i * DD + j] = acc[r][c] + bias[j];
        }
    }
}

extern "C" void kernel_launch(void* const* d_in, const int* in_sizes, int n_in,
                              void* d_out, int out_size) {
    const float* src   = (const float*)d_in[0];
    const float* in_w  = (const float*)d_in[1];
    const float* in_b  = (const float*)d_in[2];
    const float* out_w = (const float*)d_in[3];
    const float* out_b = (const float*)d_in[4];
    float* out      = (float*)d_out;
    float* attn_out = out + (size_t)SQ * BB * DD;   // [B,S,S] after [S,B,D]

    dim3 thr(16, 16);
    qkv_gemm<<<dim3(NQKV / 64, MROWS / 64), thr>>>(src, in_w, in_b);
    scores_gemm<<<dim3(SQ / 64, SQ / 64, BB * HH), thr>>>();
    softmax_rows<<<BB * HH * SQ, 256>>>();
    head_avg<<<(unsigned)(((size_t)BB * SQ * SQ + 255) / 256), 256>>>(attn_out);
    ctx_gemm<<<dim3(1, SQ / 64, BB * HH), thr>>>();
    out_gemm<<<dim3(DD / 64, MROWS / 64), thr>>>(out_w, out_b, out);
}